// round 10
// baseline (speedup 1.0000x reference)
#include <cuda_runtime.h>
#include <cstdint>

// Residual quantizer, fp32, arithmetic mirror of the reference
// (validated rel_err 7.351969e-4, all FMA chains bitwise-preserved).
// Round 10: PPT=4 (amortize code-broadcast LDS over 4 points/thread).
// Fitted model: L1% ~= 5.1 * (LDS/FMA2) * fma%. Round 6 (PPT=2) mix 0.28
// caps fma at ~70%; this mix is 5/32 = 0.156 -> L1 ceiling above the fma
// roofline. TPB=128 (4 warps/SM, 1/SMSP): latency hidden by ILP (32
// independent acc chains) + no reg cap -> no spill (regs ~160 < 255).
//  - residual in smem [dim][point], 4 consecutive pts/thread, v4 loads
//  - codebook transposed in smem, warp-uniform 16B broadcasts, 16-code tiles

#define KCODES 256
#define DIM 64
#define LEVELS 4
#define TPB 128
#define PPT 4
#define NPTS (TPB * PPT)         // 512 points per block
#define RST NPTS                 // R row stride (floats) = 512
#define CST 256                  // C row stride (floats), 1024 B rows
#define R_BYTES (DIM * RST * 4)              // 131072
#define C_BYTES (DIM * CST * 4)              // 65536
#define SMEM_BYTES (R_BYTES + C_BYTES + KCODES * 4)   // 197632

#define FMA2(d, a, b, c) \
    asm("fma.rn.f32x2 %0, %1, %2, %3;" : "=l"(d) : "l"(a), "l"(b), "l"(c))
#define DUP2(d, s) asm("mov.b64 %0, {%1, %1};" : "=l"(d) : "f"(s))
#define LDS_V2U64(a, b, addr) \
    asm("ld.shared.v2.u64 {%0,%1}, [%2];" : "=l"(a), "=l"(b) : "r"(addr))

__global__ void __launch_bounds__(TPB, 1)
rq_kernel(const float* __restrict__ z, const float* __restrict__ cb,
          float* __restrict__ out, int B) {
    extern __shared__ __align__(16) char sm_raw[];
    float* R  = reinterpret_cast<float*>(sm_raw);
    float* C  = reinterpret_cast<float*>(sm_raw + R_BYTES);
    float* c2 = reinterpret_cast<float*>(sm_raw + R_BYTES + C_BYTES);

    const int tid = threadIdx.x;
    const int lp0 = PPT * tid;               // my 4 consecutive local points
    const long pb_raw = (long)blockIdx.x * NPTS + lp0;
    long pp[PPT];
#pragma unroll
    for (int i = 0; i < PPT; i++)
        pp[i] = (pb_raw + i) < B ? (pb_raw + i) : (B - 1);

    // ---- init residual R[j][lp0+0..3] = z (4x4 transpose chunks) ----
    {
        const float4* z0 = reinterpret_cast<const float4*>(z + pp[0] * DIM);
        const float4* z1 = reinterpret_cast<const float4*>(z + pp[1] * DIM);
        const float4* z2 = reinterpret_cast<const float4*>(z + pp[2] * DIM);
        const float4* z3 = reinterpret_cast<const float4*>(z + pp[3] * DIM);
#pragma unroll
        for (int i = 0; i < 16; i++) {
            float4 a = z0[i], b = z1[i], c = z2[i], d = z3[i];
            *reinterpret_cast<float4*>(R + (4 * i + 0) * RST + lp0) =
                make_float4(a.x, b.x, c.x, d.x);
            *reinterpret_cast<float4*>(R + (4 * i + 1) * RST + lp0) =
                make_float4(a.y, b.y, c.y, d.y);
            *reinterpret_cast<float4*>(R + (4 * i + 2) * RST + lp0) =
                make_float4(a.z, b.z, c.z, d.z);
            *reinterpret_cast<float4*>(R + (4 * i + 3) * RST + lp0) =
                make_float4(a.w, b.w, c.w, d.w);
        }
    }

    const unsigned smR = (unsigned)__cvta_generic_to_shared(R) + lp0 * 4;
    const unsigned smC = (unsigned)__cvta_generic_to_shared(C);

    int ids[PPT][LEVELS];

#pragma unroll 1
    for (int lvl = 0; lvl < LEVELS; lvl++) {
        __syncthreads();   // prev level's residual update read C
        // ---- stage codebook level transposed: C[j][k] = cb[lvl][k][j] ----
#pragma unroll
        for (int k = tid; k < KCODES; k += TPB) {
            const float4* src = reinterpret_cast<const float4*>(
                cb + ((size_t)lvl * KCODES + k) * DIM);
#pragma unroll
            for (int i = 0; i < 16; i++) {
                float4 v = src[i];
                C[(4 * i + 0) * CST + k] = v.x;
                C[(4 * i + 1) * CST + k] = v.y;
                C[(4 * i + 2) * CST + k] = v.z;
                C[(4 * i + 3) * CST + k] = v.w;
            }
        }
        __syncthreads();
        // ---- c2[k]: square-then-add, sequential over dims ----
#pragma unroll
        for (int k = tid; k < KCODES; k += TPB) {
            float s = 0.f;
#pragma unroll
            for (int j = 0; j < DIM; j++) {
                float c = C[j * CST + k];
                s = __fadd_rn(s, __fmul_rn(c, c));
            }
            c2[k] = s;
        }
        __syncthreads();

        // ---- r2 for my 4 points (sequential chains) ----
        float r2[PPT] = {0.f, 0.f, 0.f, 0.f};
#pragma unroll
        for (int j = 0; j < DIM; j++) {
            float4 rv = *reinterpret_cast<const float4*>(R + j * RST + lp0);
            r2[0] = __fadd_rn(r2[0], __fmul_rn(rv.x, rv.x));
            r2[1] = __fadd_rn(r2[1], __fmul_rn(rv.y, rv.y));
            r2[2] = __fadd_rn(r2[2], __fmul_rn(rv.z, rv.z));
            r2[3] = __fadd_rn(r2[3], __fmul_rn(rv.w, rv.w));
        }

        float best[PPT];
        int bi[PPT];
#pragma unroll
        for (int i = 0; i < PPT; i++) {
            best[i] = __int_as_float(0x7F800000);
            bi[i] = 0;
        }

        // ---- distance pass: 16 tiles of 16 codes ----
#pragma unroll 1
        for (int kt = 0; kt < 16; kt++) {
            const unsigned cA = smC + kt * 64;   // 16 codes * 4 B
            unsigned long long a[PPT][8];
#pragma unroll
            for (int i = 0; i < PPT; i++)
#pragma unroll
                for (int m = 0; m < 8; m++) a[i][m] = 0ULL;

#pragma unroll 4
            for (int j = 0; j < DIM; j++) {
                float rx, ry, rz, rw;
                asm("ld.shared.v4.f32 {%0,%1,%2,%3}, [%4];"
                    : "=f"(rx), "=f"(ry), "=f"(rz), "=f"(rw)
                    : "r"(smR + j * (RST * 4)));
                unsigned long long rb[PPT];
                DUP2(rb[0], rx); DUP2(rb[1], ry);
                DUP2(rb[2], rz); DUP2(rb[3], rw);
                unsigned long long c[8];
                const unsigned ca = cA + j * (CST * 4);
                LDS_V2U64(c[0], c[1], ca);
                LDS_V2U64(c[2], c[3], ca + 16);
                LDS_V2U64(c[4], c[5], ca + 32);
                LDS_V2U64(c[6], c[7], ca + 48);
#pragma unroll
                for (int i = 0; i < PPT; i++)
#pragma unroll
                    for (int m = 0; m < 8; m++)
                        FMA2(a[i][m], rb[i], c[m], a[i][m]);
            }
            // ---- distances + argmin (ascending k, strict < => first-min)
#pragma unroll
            for (int m = 0; m < 8; m++) {
                const int k0 = kt * 16 + 2 * m;
                const float cc0 = c2[k0], cc1 = c2[k0 + 1];
#pragma unroll
                for (int i = 0; i < PPT; i++) {
                    float lo, hi;
                    asm("mov.b64 {%0,%1}, %2;"
                        : "=f"(lo), "=f"(hi) : "l"(a[i][m]));
                    float d0 = __fadd_rn(
                        __fsub_rn(r2[i], __fmul_rn(2.0f, lo)), cc0);
                    float d1 = __fadd_rn(
                        __fsub_rn(r2[i], __fmul_rn(2.0f, hi)), cc1);
                    if (d0 < best[i]) { best[i] = d0; bi[i] = k0; }
                    if (d1 < best[i]) { best[i] = d1; bi[i] = k0 + 1; }
                }
            }
        }
#pragma unroll
        for (int i = 0; i < PPT; i++) ids[i][lvl] = bi[i];

        // ---- residual update (reads C; next sync at loop top) ----
#pragma unroll
        for (int j = 0; j < DIM; j++) {
            float4 rv = *reinterpret_cast<const float4*>(R + j * RST + lp0);
            rv.x = __fsub_rn(rv.x, C[j * CST + bi[0]]);
            rv.y = __fsub_rn(rv.y, C[j * CST + bi[1]]);
            rv.z = __fsub_rn(rv.z, C[j * CST + bi[2]]);
            rv.w = __fsub_rn(rv.w, C[j * CST + bi[3]]);
            *reinterpret_cast<float4*>(R + j * RST + lp0) = rv;
        }
    }

    // ---- epilogue (chunk-wise; validated bitwise vs reference) ----
#pragma unroll 1
    for (int s = 0; s < PPT; s++) {
        if ((pb_raw + s) >= B) continue;
        const long p = pp[s];
        const int* id = ids[s];
        const float4* cp0 = reinterpret_cast<const float4*>(
            cb + ((size_t)0 * KCODES + id[0]) * DIM);
        const float4* cp1 = reinterpret_cast<const float4*>(
            cb + ((size_t)1 * KCODES + id[1]) * DIM);
        const float4* cp2 = reinterpret_cast<const float4*>(
            cb + ((size_t)2 * KCODES + id[2]) * DIM);
        const float4* cp3 = reinterpret_cast<const float4*>(
            cb + ((size_t)3 * KCODES + id[3]) * DIM);
        const float4* zp = reinterpret_cast<const float4*>(z + p * DIM);
        float4* qst = reinterpret_cast<float4*>(out + (size_t)p * DIM);
        float4* qq  = reinterpret_cast<float4*>(out + (size_t)B * (DIM + 4) +
                                                (size_t)p * DIM);
#pragma unroll
        for (int i = 0; i < 16; i++) {
            float4 v0 = __ldg(cp0 + i), v1 = __ldg(cp1 + i);
            float4 v2 = __ldg(cp2 + i), v3 = __ldg(cp3 + i);
            // quantized = ((q0 + q1) + q2) + q3, sequential (matches ref)
            float4 qv;
            qv.x = __fadd_rn(__fadd_rn(__fadd_rn(v0.x, v1.x), v2.x), v3.x);
            qv.y = __fadd_rn(__fadd_rn(__fadd_rn(v0.y, v1.y), v2.y), v3.y);
            qv.z = __fadd_rn(__fadd_rn(__fadd_rn(v0.z, v1.z), v2.z), v3.z);
            qv.w = __fadd_rn(__fadd_rn(__fadd_rn(v0.w, v1.w), v2.w), v3.w);
            float4 zv = zp[i];
            float4 sv;
            sv.x = __fadd_rn(zv.x, __fsub_rn(qv.x, zv.x));
            sv.y = __fadd_rn(zv.y, __fsub_rn(qv.y, zv.y));
            sv.z = __fadd_rn(zv.z, __fsub_rn(qv.z, zv.z));
            sv.w = __fadd_rn(zv.w, __fsub_rn(qv.w, zv.w));
            qst[i] = sv;
            qq[i] = qv;
        }
        float4 iv;
        iv.x = (float)id[0]; iv.y = (float)id[1];
        iv.z = (float)id[2]; iv.w = (float)id[3];
        reinterpret_cast<float4*>(out + (size_t)B * DIM)[p] = iv;
    }
}

extern "C" void kernel_launch(void* const* d_in, const int* in_sizes, int n_in,
                              void* d_out, int out_size) {
    const float* z = (const float*)d_in[0];
    const float* cb = (const float*)d_in[1];
    float* out = (float*)d_out;
    int B = in_sizes[0] / DIM;

    cudaFuncSetAttribute(rq_kernel, cudaFuncAttributeMaxDynamicSharedMemorySize,
                         SMEM_BYTES);
    int blocks = (B + NPTS - 1) / NPTS;
    rq_kernel<<<blocks, TPB, SMEM_BYTES>>>(z, cb, out, B);
}

// round 11
// speedup vs baseline: 1.5007x; 1.5007x over previous
#include <cuda_runtime.h>
#include <cstdint>

// Residual quantizer, fp32, arithmetic mirror of the reference
// (validated rel_err 7.351969e-4, all FMA chains bitwise-preserved).
// Round 11: PPT=4 mix (L1-safe, proven round 10) + register headroom +
// more warps:
//  * 8-code tiles: 32 acc regs (vs 64) -> ~130 live regs, ptxas can
//    software-pipeline the LDS->FMA dependency (round 10: regs=255, no
//    pipelining, issue 24.9%).
//  * codebook streamed in TWO HALVES of 128 codes (C smem 32K): frees room
//    for TPB=192 -> 6 warps/SM. best/bi carried across halves ascending-k.
//  * residual update gathers chosen codes from gmem (bitwise-same values;
//    half-0 C is overwritten by half 1).

#define KCODES 256
#define DIM 64
#define LEVELS 4
#define TPB 192
#define PPT 4
#define NPTS (TPB * PPT)         // 768 points per block
#define RST NPTS                 // R row stride (floats) = 768
#define KHALF 128                // codes per staged half
#define CST KHALF                // C row stride (floats), 512 B rows
#define R_BYTES (DIM * RST * 4)              // 196608
#define C_BYTES (DIM * CST * 4)              // 32768
#define SMEM_BYTES (R_BYTES + C_BYTES + KCODES * 4)   // 230400

#define FMA2(d, a, b, c) \
    asm("fma.rn.f32x2 %0, %1, %2, %3;" : "=l"(d) : "l"(a), "l"(b), "l"(c))
#define DUP2(d, s) asm("mov.b64 %0, {%1, %1};" : "=l"(d) : "f"(s))
#define LDS_V2U64(a, b, addr) \
    asm("ld.shared.v2.u64 {%0,%1}, [%2];" : "=l"(a), "=l"(b) : "r"(addr))

__global__ void __launch_bounds__(TPB, 1)
rq_kernel(const float* __restrict__ z, const float* __restrict__ cb,
          float* __restrict__ out, int B) {
    extern __shared__ __align__(16) char sm_raw[];
    float* R  = reinterpret_cast<float*>(sm_raw);
    float* C  = reinterpret_cast<float*>(sm_raw + R_BYTES);
    float* c2 = reinterpret_cast<float*>(sm_raw + R_BYTES + C_BYTES);

    const int tid = threadIdx.x;
    const int lp0 = PPT * tid;
    const long pb_raw = (long)blockIdx.x * NPTS + lp0;
    long pp[PPT];
#pragma unroll
    for (int i = 0; i < PPT; i++)
        pp[i] = (pb_raw + i) < B ? (pb_raw + i) : (B - 1);

    // ---- init residual R[j][lp0+0..3] = z ----
    {
        const float4* z0 = reinterpret_cast<const float4*>(z + pp[0] * DIM);
        const float4* z1 = reinterpret_cast<const float4*>(z + pp[1] * DIM);
        const float4* z2 = reinterpret_cast<const float4*>(z + pp[2] * DIM);
        const float4* z3 = reinterpret_cast<const float4*>(z + pp[3] * DIM);
#pragma unroll
        for (int i = 0; i < 16; i++) {
            float4 a = z0[i], b = z1[i], c = z2[i], d = z3[i];
            *reinterpret_cast<float4*>(R + (4 * i + 0) * RST + lp0) =
                make_float4(a.x, b.x, c.x, d.x);
            *reinterpret_cast<float4*>(R + (4 * i + 1) * RST + lp0) =
                make_float4(a.y, b.y, c.y, d.y);
            *reinterpret_cast<float4*>(R + (4 * i + 2) * RST + lp0) =
                make_float4(a.z, b.z, c.z, d.z);
            *reinterpret_cast<float4*>(R + (4 * i + 3) * RST + lp0) =
                make_float4(a.w, b.w, c.w, d.w);
        }
    }

    const unsigned smR = (unsigned)__cvta_generic_to_shared(R) + lp0 * 4;
    const unsigned smC = (unsigned)__cvta_generic_to_shared(C);

    int ids[PPT][LEVELS];

#pragma unroll 1
    for (int lvl = 0; lvl < LEVELS; lvl++) {
        float r2[PPT];
        float best[PPT];
        int bi[PPT];

#pragma unroll 1
        for (int half = 0; half < 2; half++) {
            __syncthreads();   // everyone done reading prev C contents
            // ---- stage half: C[j][k] = cb[lvl][half*128+k][j], k<128 ----
            if (tid < KHALF) {
                const int gk = half * KHALF + tid;
                const float4* src = reinterpret_cast<const float4*>(
                    cb + ((size_t)lvl * KCODES + gk) * DIM);
#pragma unroll
                for (int i = 0; i < 16; i++) {
                    float4 v = src[i];
                    C[(4 * i + 0) * CST + tid] = v.x;
                    C[(4 * i + 1) * CST + tid] = v.y;
                    C[(4 * i + 2) * CST + tid] = v.z;
                    C[(4 * i + 3) * CST + tid] = v.w;
                }
                // c2: square-then-add, sequential over dims
                float s = 0.f;
#pragma unroll
                for (int j = 0; j < DIM; j++) {
                    float c = C[j * CST + tid];
                    s = __fadd_rn(s, __fmul_rn(c, c));
                }
                c2[gk] = s;
            }
            __syncthreads();

            if (half == 0) {
                // ---- r2 for my 4 points (sequential chains) ----
#pragma unroll
                for (int i = 0; i < PPT; i++) r2[i] = 0.f;
#pragma unroll
                for (int j = 0; j < DIM; j++) {
                    float4 rv =
                        *reinterpret_cast<const float4*>(R + j * RST + lp0);
                    r2[0] = __fadd_rn(r2[0], __fmul_rn(rv.x, rv.x));
                    r2[1] = __fadd_rn(r2[1], __fmul_rn(rv.y, rv.y));
                    r2[2] = __fadd_rn(r2[2], __fmul_rn(rv.z, rv.z));
                    r2[3] = __fadd_rn(r2[3], __fmul_rn(rv.w, rv.w));
                }
#pragma unroll
                for (int i = 0; i < PPT; i++) {
                    best[i] = __int_as_float(0x7F800000);
                    bi[i] = 0;
                }
            }

            // ---- distance pass: 16 tiles of 8 codes ----
#pragma unroll 1
            for (int kt = 0; kt < 16; kt++) {
                const unsigned cA = smC + kt * 32;    // 8 codes * 4 B
                unsigned long long a[PPT][4];
#pragma unroll
                for (int i = 0; i < PPT; i++)
#pragma unroll
                    for (int m = 0; m < 4; m++) a[i][m] = 0ULL;

#pragma unroll 8
                for (int j = 0; j < DIM; j++) {
                    float rx, ry, rz, rw;
                    asm("ld.shared.v4.f32 {%0,%1,%2,%3}, [%4];"
                        : "=f"(rx), "=f"(ry), "=f"(rz), "=f"(rw)
                        : "r"(smR + j * (RST * 4)));
                    unsigned long long c[4];
                    const unsigned ca = cA + j * (CST * 4);
                    LDS_V2U64(c[0], c[1], ca);
                    LDS_V2U64(c[2], c[3], ca + 16);
                    unsigned long long rb[PPT];
                    DUP2(rb[0], rx); DUP2(rb[1], ry);
                    DUP2(rb[2], rz); DUP2(rb[3], rw);
#pragma unroll
                    for (int i = 0; i < PPT; i++)
#pragma unroll
                        for (int m = 0; m < 4; m++)
                            FMA2(a[i][m], rb[i], c[m], a[i][m]);
                }
                // ---- distances + argmin (ascending k, strict <) ----
#pragma unroll
                for (int m = 0; m < 4; m++) {
                    const int k0 = half * KHALF + kt * 8 + 2 * m;
                    const float cc0 = c2[k0], cc1 = c2[k0 + 1];
#pragma unroll
                    for (int i = 0; i < PPT; i++) {
                        float lo, hi;
                        asm("mov.b64 {%0,%1}, %2;"
                            : "=f"(lo), "=f"(hi) : "l"(a[i][m]));
                        float d0 = __fadd_rn(
                            __fsub_rn(r2[i], __fmul_rn(2.0f, lo)), cc0);
                        float d1 = __fadd_rn(
                            __fsub_rn(r2[i], __fmul_rn(2.0f, hi)), cc1);
                        if (d0 < best[i]) { best[i] = d0; bi[i] = k0; }
                        if (d1 < best[i]) { best[i] = d1; bi[i] = k0 + 1; }
                    }
                }
            }
        }
#pragma unroll
        for (int i = 0; i < PPT; i++) ids[i][lvl] = bi[i];

        // ---- residual update: gather chosen codes from GMEM (bitwise-same
        // values as the smem copy; half-0 C was overwritten by half 1) ----
        {
            const float4* cp[PPT];
#pragma unroll
            for (int i = 0; i < PPT; i++)
                cp[i] = reinterpret_cast<const float4*>(
                    cb + ((size_t)lvl * KCODES + bi[i]) * DIM);
#pragma unroll
            for (int cch = 0; cch < 16; cch++) {
                float4 v0 = __ldg(cp[0] + cch);
                float4 v1 = __ldg(cp[1] + cch);
                float4 v2 = __ldg(cp[2] + cch);
                float4 v3 = __ldg(cp[3] + cch);
                float cu[4][4] = {{v0.x, v1.x, v2.x, v3.x},
                                  {v0.y, v1.y, v2.y, v3.y},
                                  {v0.z, v1.z, v2.z, v3.z},
                                  {v0.w, v1.w, v2.w, v3.w}};
#pragma unroll
                for (int u = 0; u < 4; u++) {
                    const int j = 4 * cch + u;
                    float4 rv =
                        *reinterpret_cast<const float4*>(R + j * RST + lp0);
                    rv.x = __fsub_rn(rv.x, cu[u][0]);
                    rv.y = __fsub_rn(rv.y, cu[u][1]);
                    rv.z = __fsub_rn(rv.z, cu[u][2]);
                    rv.w = __fsub_rn(rv.w, cu[u][3]);
                    *reinterpret_cast<float4*>(R + j * RST + lp0) = rv;
                }
            }
        }
    }

    // ---- epilogue (chunk-wise; validated bitwise vs reference) ----
#pragma unroll 1
    for (int s = 0; s < PPT; s++) {
        if ((pb_raw + s) >= B) continue;
        const long p = pp[s];
        const int* id = ids[s];
        const float4* cp0 = reinterpret_cast<const float4*>(
            cb + ((size_t)0 * KCODES + id[0]) * DIM);
        const float4* cp1 = reinterpret_cast<const float4*>(
            cb + ((size_t)1 * KCODES + id[1]) * DIM);
        const float4* cp2 = reinterpret_cast<const float4*>(
            cb + ((size_t)2 * KCODES + id[2]) * DIM);
        const float4* cp3 = reinterpret_cast<const float4*>(
            cb + ((size_t)3 * KCODES + id[3]) * DIM);
        const float4* zp = reinterpret_cast<const float4*>(z + p * DIM);
        float4* qst = reinterpret_cast<float4*>(out + (size_t)p * DIM);
        float4* qq  = reinterpret_cast<float4*>(out + (size_t)B * (DIM + 4) +
                                                (size_t)p * DIM);
#pragma unroll
        for (int i = 0; i < 16; i++) {
            float4 v0 = __ldg(cp0 + i), v1 = __ldg(cp1 + i);
            float4 v2 = __ldg(cp2 + i), v3 = __ldg(cp3 + i);
            // quantized = ((q0 + q1) + q2) + q3, sequential (matches ref)
            float4 qv;
            qv.x = __fadd_rn(__fadd_rn(__fadd_rn(v0.x, v1.x), v2.x), v3.x);
            qv.y = __fadd_rn(__fadd_rn(__fadd_rn(v0.y, v1.y), v2.y), v3.y);
            qv.z = __fadd_rn(__fadd_rn(__fadd_rn(v0.z, v1.z), v2.z), v3.z);
            qv.w = __fadd_rn(__fadd_rn(__fadd_rn(v0.w, v1.w), v2.w), v3.w);
            float4 zv = zp[i];
            float4 sv;
            sv.x = __fadd_rn(zv.x, __fsub_rn(qv.x, zv.x));
            sv.y = __fadd_rn(zv.y, __fsub_rn(qv.y, zv.y));
            sv.z = __fadd_rn(zv.z, __fsub_rn(qv.z, zv.z));
            sv.w = __fadd_rn(zv.w, __fsub_rn(qv.w, zv.w));
            qst[i] = sv;
            qq[i] = qv;
        }
        float4 iv;
        iv.x = (float)id[0]; iv.y = (float)id[1];
        iv.z = (float)id[2]; iv.w = (float)id[3];
        reinterpret_cast<float4*>(out + (size_t)B * DIM)[p] = iv;
    }
}

extern "C" void kernel_launch(void* const* d_in, const int* in_sizes, int n_in,
                              void* d_out, int out_size) {
    const float* z = (const float*)d_in[0];
    const float* cb = (const float*)d_in[1];
    float* out = (float*)d_out;
    int B = in_sizes[0] / DIM;

    cudaFuncSetAttribute(rq_kernel, cudaFuncAttributeMaxDynamicSharedMemorySize,
                         SMEM_BYTES);
    int blocks = (B + NPTS - 1) / NPTS;
    rq_kernel<<<blocks, TPB, SMEM_BYTES>>>(z, cb, out, B);
}